// round 12
// baseline (speedup 1.0000x reference)
#include <cuda_runtime.h>
#include <math.h>

#define B_   64
#define C_   32
#define L_   1549
#define S_   512
#define HID_ 256
#define G4_  1024
#define D2_  512
#define NH_  8

// ------------------------- scratch (device globals) -------------------------
__device__ float g_h0 [(size_t)B_*S_*C_];
__device__ float g_xgf[(size_t)B_*S_*G4_];
__device__ float g_xgb[(size_t)B_*S_*G4_];
__device__ float g_out0[(size_t)B_*S_*D2_];
__device__ float g_out1[(size_t)B_*S_*D2_];
__device__ float g_q[(size_t)B_*S_*D2_];
__device__ float g_k[(size_t)B_*S_*D2_];
__device__ float g_v[(size_t)B_*S_*D2_];
__device__ float g_attn[(size_t)B_*NH_*S_*S_];
__device__ float g_ctx[(size_t)B_*S_*D2_];
__device__ float g_r[(size_t)B_*S_*D2_];

__device__ float g_wcT[C_*16*C_];
__device__ float g_wih0fT[C_*G4_],  g_wih0bT[C_*G4_];
__device__ float g_wih1fT[D2_*G4_], g_wih1bT[D2_*G4_];
__device__ float g_whh0fI[HID_*G4_], g_whh0bI[HID_*G4_];
__device__ float g_whh1fI[HID_*G4_], g_whh1bI[HID_*G4_];
__device__ float g_wqT[D2_*D2_], g_wkT[D2_*D2_], g_wvT[D2_*D2_];

__device__ __forceinline__ float sigm_(float x) { return 1.f/(1.f+__expf(-x)); }

__device__ __forceinline__ float blockReduceSum(float v) {
    __shared__ float sh[32];
    __syncthreads();
    int lane = threadIdx.x & 31, w = threadIdx.x >> 5;
    #pragma unroll
    for (int o = 16; o; o >>= 1) v += __shfl_down_sync(0xffffffffu, v, o);
    if (!lane) sh[w] = v;
    __syncthreads();
    if (w == 0) {
        int nw = blockDim.x >> 5;
        v = (lane < nw) ? sh[lane] : 0.f;
        #pragma unroll
        for (int o = 16; o; o >>= 1) v += __shfl_down_sync(0xffffffffu, v, o);
        if (!lane) sh[0] = v;
    }
    __syncthreads();
    return sh[0];
}

// ------------------------- weight reshapes -------------------------
// generic (N,K) row-major -> (K,N) row-major
__global__ void transpose_k(const float* __restrict__ in, float* __restrict__ out,
                            int N, int K) {
    int idx = blockIdx.x*blockDim.x + threadIdx.x;
    if (idx < N*K) {
        int n = idx % N, k = idx / N;
        out[idx] = in[(size_t)n*K + k];
    }
}
// conv_w (O=32, I=32, K=16) -> wcT[i][k][o]
__global__ void convw_t_k(const float* __restrict__ in, float* __restrict__ out) {
    int idx = blockIdx.x*blockDim.x + threadIdx.x;
    if (idx < C_*16*C_) {
        int o = idx % C_, k = (idx / C_) % 16, i = idx / (C_*16);
        out[idx] = in[((size_t)o*C_ + i)*16 + k];
    }
}
// W_hh (1024,256) -> interleaved [k][4*j+g] = W[g*256+j][k]
__global__ void whh_int_k(const float* __restrict__ in, float* __restrict__ out) {
    int idx = blockIdx.x*blockDim.x + threadIdx.x;
    if (idx < HID_*G4_) {
        int col = idx % G4_, k = idx / G4_;
        int j = col >> 2, g = col & 3;
        out[idx] = in[((size_t)g*HID_ + j)*HID_ + k];
    }
}

// ------------------------- conv1d + bn + relu + maxpool3 -------------------------
// grid (S/4, B), block 128: tid = si*32 + c ; h0 layout [B][S][C]
__global__ void conv_bn_pool_k(const float* __restrict__ x, const float* __restrict__ wcT,
                               const float* __restrict__ cb, const float* __restrict__ gma,
                               const float* __restrict__ bta, const float* __restrict__ mean,
                               const float* __restrict__ var, float* __restrict__ h0) {
    int c  = threadIdx.x & 31;
    int si = threadIdx.x >> 5;
    int s  = (blockIdx.x << 2) + si;
    int b  = blockIdx.y;
    float scale = gma[c] * rsqrtf(var[c] + 1e-5f);
    float shift = bta[c] - mean[c]*scale;
    float a0 = cb[c], a1 = cb[c], a2 = cb[c];
    const float* xb = x + (size_t)b*C_*L_;
    int l0 = 3*s - 1;
    for (int ci = 0; ci < C_; ++ci) {
        const float* xc = xb + (size_t)ci*L_;
        float xv[18];
        #pragma unroll
        for (int qd = 0; qd < 18; ++qd) {
            int idx = l0 + qd;
            xv[qd] = (idx >= 0 && idx < L_) ? xc[idx] : 0.f;
        }
        const float* w = wcT + (size_t)ci*16*C_ + c;
        #pragma unroll
        for (int kk = 0; kk < 16; ++kk) {
            float wv = w[(size_t)kk*C_];
            a0 = fmaf(xv[kk+0], wv, a0);
            a1 = fmaf(xv[kk+1], wv, a1);
            a2 = fmaf(xv[kk+2], wv, a2);
        }
    }
    a0 = fmaxf(fmaf(a0, scale, shift), 0.f);
    a1 = fmaxf(fmaf(a1, scale, shift), 0.f);
    a2 = fmaxf(fmaf(a2, scale, shift), 0.f);
    h0[((size_t)b*S_ + s)*C_ + c] = fmaxf(a0, fmaxf(a1, a2));
}

// ------------------------- SGEMM: C = A(MxK) @ Bm(KxN) + bias -------------------------
// 128x128 tile, BK=8, 256 threads, 8x8 microtile. M,N mult of 128; K mult of 8.
__global__ void __launch_bounds__(256) sgemm_bias_k(
    const float* __restrict__ A, const float* __restrict__ Bm,
    const float* __restrict__ bias, float* __restrict__ C,
    int M, int N, int K) {
    __shared__ float As[8][128];
    __shared__ float Bs[8][128];
    int tid = threadIdx.x;
    int m0 = blockIdx.y << 7;
    int n0 = blockIdx.x << 7;
    int arow = tid >> 1, acol = (tid & 1) << 2;
    int brow = tid >> 5, bcol = (tid & 31) << 2;
    int tr = tid >> 4, tc = tid & 15;
    float acc[8][8];
    #pragma unroll
    for (int i = 0; i < 8; ++i)
        #pragma unroll
        for (int j = 0; j < 8; ++j) acc[i][j] = 0.f;

    const float* Ap = A + (size_t)(m0 + arow)*K + acol;
    const float* Bp = Bm + (size_t)brow*N + n0 + bcol;
    for (int k0 = 0; k0 < K; k0 += 8) {
        float4 av = *(const float4*)(Ap + k0);
        float4 bv = *(const float4*)(Bp + (size_t)k0*N);
        As[acol+0][arow] = av.x; As[acol+1][arow] = av.y;
        As[acol+2][arow] = av.z; As[acol+3][arow] = av.w;
        *(float4*)&Bs[brow][bcol] = bv;
        __syncthreads();
        #pragma unroll
        for (int kk = 0; kk < 8; ++kk) {
            float a[8], b[8];
            *(float4*)(a)   = *(const float4*)&As[kk][tr*8];
            *(float4*)(a+4) = *(const float4*)&As[kk][tr*8+4];
            *(float4*)(b)   = *(const float4*)&Bs[kk][tc*8];
            *(float4*)(b+4) = *(const float4*)&Bs[kk][tc*8+4];
            #pragma unroll
            for (int i = 0; i < 8; ++i)
                #pragma unroll
                for (int j = 0; j < 8; ++j)
                    acc[i][j] = fmaf(a[i], b[j], acc[i][j]);
        }
        __syncthreads();
    }
    #pragma unroll
    for (int i = 0; i < 8; ++i) {
        float* Cp = C + (size_t)(m0 + tr*8 + i)*N + n0 + tc*8;
        #pragma unroll
        for (int j = 0; j < 8; ++j)
            Cp[j] = acc[i][j] + bias[n0 + tc*8 + j];
    }
}

// ------------------------- BiLSTM recurrence -------------------------
// grid (B/2, 2 dirs), block 256. whhI interleaved: [k][4*j + {i,f,g,o}].
// xg layout [b][t][1024] with gate blocks i|f|g|o of 256.
__global__ void __launch_bounds__(256) lstm_k(
    const float* __restrict__ xgf, const float* __restrict__ xgb,
    const float* __restrict__ whhfI, const float* __restrict__ whhbI,
    float* __restrict__ out) {
    int tid = threadIdx.x;
    int dir = blockIdx.y;
    int b0  = blockIdx.x << 1;
    const float* xg = dir ? xgb : xgf;
    const float* w  = dir ? whhbI : whhfI;
    __shared__ float hs[2][HID_];
    hs[0][tid] = 0.f; hs[1][tid] = 0.f;
    float c0 = 0.f, c1 = 0.f;
    for (int step = 0; step < S_; ++step) {
        __syncthreads();
        float a00=0.f,a01=0.f,a02=0.f,a03=0.f;
        float a10=0.f,a11=0.f,a12=0.f,a13=0.f;
        const float* wp = w + 4*tid;
        #pragma unroll 16
        for (int k = 0; k < HID_; ++k) {
            float h0v = hs[0][k], h1v = hs[1][k];
            float4 w4 = *(const float4*)(wp + (size_t)k*G4_);
            a00 = fmaf(h0v, w4.x, a00); a10 = fmaf(h1v, w4.x, a10);
            a01 = fmaf(h0v, w4.y, a01); a11 = fmaf(h1v, w4.y, a11);
            a02 = fmaf(h0v, w4.z, a02); a12 = fmaf(h1v, w4.z, a12);
            a03 = fmaf(h0v, w4.w, a03); a13 = fmaf(h1v, w4.w, a13);
        }
        int t = dir ? (S_-1-step) : step;
        const float* x0 = xg + ((size_t)b0    *S_ + t)*G4_;
        const float* x1 = xg + ((size_t)(b0+1)*S_ + t)*G4_;
        a00 += x0[tid]; a01 += x0[tid+256]; a02 += x0[tid+512]; a03 += x0[tid+768];
        a10 += x1[tid]; a11 += x1[tid+256]; a12 += x1[tid+512]; a13 += x1[tid+768];
        c0 = sigm_(a01)*c0 + sigm_(a00)*tanhf(a02);
        float h0n = sigm_(a03)*tanhf(c0);
        c1 = sigm_(a11)*c1 + sigm_(a10)*tanhf(a12);
        float h1n = sigm_(a13)*tanhf(c1);
        __syncthreads();
        hs[0][tid] = h0n; hs[1][tid] = h1n;
        out[((size_t)b0    *S_ + t)*D2_ + dir*HID_ + tid] = h0n;
        out[((size_t)(b0+1)*S_ + t)*D2_ + dir*HID_ + tid] = h1n;
    }
}

// ------------------------- attention scores -------------------------
// grid (t-tiles=8, s-tiles=8, B*NH), block 256. attn[b][h][s][t] = q.k/8
__global__ void __launch_bounds__(256) attn_scores_k(
    const float* __restrict__ q, const float* __restrict__ k,
    float* __restrict__ attn) {
    __shared__ float Qs[64][65];
    __shared__ float Ks[64][65];
    int tid = threadIdx.x;
    int bh = blockIdx.z; int b = bh >> 3, h = bh & 7;
    int s0 = blockIdx.y << 6, t0 = blockIdx.x << 6;
    const float* qb = q + ((size_t)b*S_ + s0)*D2_ + h*64;
    const float* kb = k + ((size_t)b*S_ + t0)*D2_ + h*64;
    for (int i = tid; i < 64*64; i += 256) {
        int r = i >> 6, cc = i & 63;
        Qs[r][cc] = qb[(size_t)r*D2_ + cc];
        Ks[r][cc] = kb[(size_t)r*D2_ + cc];
    }
    __syncthreads();
    int tr = tid >> 4, tc = tid & 15;
    float acc[4][4];
    #pragma unroll
    for (int i = 0; i < 4; ++i)
        #pragma unroll
        for (int j = 0; j < 4; ++j) acc[i][j] = 0.f;
    #pragma unroll 4
    for (int d = 0; d < 64; ++d) {
        float qa[4], ka[4];
        #pragma unroll
        for (int i = 0; i < 4; ++i) qa[i] = Qs[tr*4+i][d];
        #pragma unroll
        for (int j = 0; j < 4; ++j) ka[j] = Ks[tc*4+j][d];
        #pragma unroll
        for (int i = 0; i < 4; ++i)
            #pragma unroll
            for (int j = 0; j < 4; ++j)
                acc[i][j] = fmaf(qa[i], ka[j], acc[i][j]);
    }
    float* ap = attn + (((size_t)bh*S_ + s0 + tr*4)*S_ + t0 + tc*4);
    #pragma unroll
    for (int i = 0; i < 4; ++i)
        #pragma unroll
        for (int j = 0; j < 4; ++j)
            ap[(size_t)i*S_ + j] = acc[i][j] * 0.125f;
}

// ------------------------- log-softmax over heads (axis=1) -------------------------
__global__ void logsoftmax_h_k(float* __restrict__ attn) {
    size_t idx = (size_t)blockIdx.x*blockDim.x + threadIdx.x;
    size_t total = (size_t)B_*S_*S_;
    if (idx >= total) return;
    int t = idx & (S_-1);
    int s = (idx >> 9) & (S_-1);
    int b = idx >> 18;
    float* p = attn + (((size_t)b*NH_)*S_ + s)*S_ + t;
    const size_t hs = (size_t)S_*S_;
    float v[NH_];
    float m = -1e30f;
    #pragma unroll
    for (int h = 0; h < NH_; ++h) { v[h] = p[h*hs]; m = fmaxf(m, v[h]); }
    float sum = 0.f;
    #pragma unroll
    for (int h = 0; h < NH_; ++h) sum += __expf(v[h] - m);
    float lse = __logf(sum) + m;
    #pragma unroll
    for (int h = 0; h < NH_; ++h) p[h*hs] = v[h] - lse;
}

// ------------------------- ctx = la @ v -------------------------
// grid (s-tiles=8, B*NH), block 256. ctx stored [b][s][h*64+d]
__global__ void __launch_bounds__(256) attn_ctx_k(
    const float* __restrict__ la, const float* __restrict__ v,
    float* __restrict__ ctx) {
    __shared__ float Ls[64][65];
    __shared__ float Vs[64][65];
    int tid = threadIdx.x;
    int bh = blockIdx.y; int b = bh >> 3, h = bh & 7;
    int s0 = blockIdx.x << 6;
    int tr = tid >> 4, tc = tid & 15;
    float acc[4][4];
    #pragma unroll
    for (int i = 0; i < 4; ++i)
        #pragma unroll
        for (int j = 0; j < 4; ++j) acc[i][j] = 0.f;
    for (int t0 = 0; t0 < S_; t0 += 64) {
        for (int i = tid; i < 64*64; i += 256) {
            int r = i >> 6, cc = i & 63;
            Ls[r][cc] = la[(((size_t)bh*S_) + s0 + r)*S_ + t0 + cc];
            Vs[r][cc] = v[((size_t)b*S_ + t0 + r)*D2_ + h*64 + cc];
        }
        __syncthreads();
        #pragma unroll 4
        for (int kk = 0; kk < 64; ++kk) {
            float a[4], bb[4];
            #pragma unroll
            for (int i = 0; i < 4; ++i) a[i] = Ls[tr*4+i][kk];
            #pragma unroll
            for (int j = 0; j < 4; ++j) bb[j] = Vs[kk][tc*4+j];
            #pragma unroll
            for (int i = 0; i < 4; ++i)
                #pragma unroll
                for (int j = 0; j < 4; ++j)
                    acc[i][j] = fmaf(a[i], bb[j], acc[i][j]);
        }
        __syncthreads();
    }
    #pragma unroll
    for (int i = 0; i < 4; ++i) {
        float* cp = ctx + ((size_t)b*S_ + s0 + tr*4 + i)*D2_ + h*64 + tc*4;
        #pragma unroll
        for (int j = 0; j < 4; ++j) cp[j] = acc[i][j];
    }
}

// ------------------------- residual + layernorm -------------------------
// grid B*S, block 256
__global__ void __launch_bounds__(256) res_ln_k(
    const float* __restrict__ out1, const float* __restrict__ ctx,
    const float* __restrict__ lng, const float* __restrict__ lnb,
    float* __restrict__ r) {
    size_t row = blockIdx.x;
    int tid = threadIdx.x;
    const float* o = out1 + row*D2_;
    const float* c = ctx  + row*D2_;
    float v0 = o[tid] + c[tid];
    float v1 = o[tid+256] + c[tid+256];
    float mu = blockReduceSum(v0 + v1) * (1.f/D2_);
    float d0 = v0 - mu, d1 = v1 - mu;
    float var = blockReduceSum(d0*d0 + d1*d1) * (1.f/D2_);
    float rs = rsqrtf(var + 1e-5f);
    r[row*D2_ + tid]       = d0*rs*lng[tid]     + lnb[tid];
    r[row*D2_ + tid + 256] = d1*rs*lng[tid+256] + lnb[tid+256];
}

// ------------------------- mean pool + fc -------------------------
// grid B, block 256
__global__ void __launch_bounds__(256) pool_fc_k(
    const float* __restrict__ r, const float* __restrict__ fcw,
    const float* __restrict__ fcb, float* __restrict__ out) {
    int b = blockIdx.x, tid = threadIdx.x;
    const float* rb = r + (size_t)b*S_*D2_;
    float acc = 0.f;
    for (int i = tid; i < S_*D2_; i += 256)
        acc = fmaf(rb[i], fcw[i & (D2_-1)], acc);
    float total = blockReduceSum(acc);
    if (tid == 0) out[b] = total * (1.f/S_) + fcb[0];
}

// ------------------------- launch -------------------------
static float* devptr(const void* sym) {
    void* p = nullptr;
    cudaGetSymbolAddress(&p, sym);
    return (float*)p;
}

extern "C" void kernel_launch(void* const* d_in, const int* in_sizes, int n_in,
                              void* d_out, int out_size) {
    const float* x       = (const float*)d_in[0];
    const float* conv_w  = (const float*)d_in[1];
    const float* conv_b  = (const float*)d_in[2];
    const float* bn_g    = (const float*)d_in[3];
    const float* bn_b    = (const float*)d_in[4];
    const float* bn_m    = (const float*)d_in[5];
    const float* bn_v    = (const float*)d_in[6];
    const float* W_ih0f  = (const float*)d_in[7];
    const float* W_hh0f  = (const float*)d_in[8];
    const float* b0f     = (const float*)d_in[9];
    const float* W_ih0b  = (const float*)d_in[10];
    const float* W_hh0b  = (const float*)d_in[11];
    const float* b0b     = (const float*)d_in[12];
    const float* W_ih1f  = (const float*)d_in[13];
    const float* W_hh1f  = (const float*)d_in[14];
    const float* b1f     = (const float*)d_in[15];
    const float* W_ih1b  = (const float*)d_in[16];
    const float* W_hh1b  = (const float*)d_in[17];
    const float* b1b     = (const float*)d_in[18];
    const float* Wq      = (const float*)d_in[19];
    const float* bq      = (const float*)d_in[20];
    const float* Wk      = (const float*)d_in[21];
    const float* bk      = (const float*)d_in[22];
    const float* Wv      = (const float*)d_in[23];
    const float* bv      = (const float*)d_in[24];
    const float* ln_g    = (const float*)d_in[25];
    const float* ln_b    = (const float*)d_in[26];
    const float* fc_w    = (const float*)d_in[27];
    const float* fc_b    = (const float*)d_in[28];
    float* out = (float*)d_out;

    float* p_h0   = devptr(g_h0);
    float* p_xgf  = devptr(g_xgf);
    float* p_xgb  = devptr(g_xgb);
    float* p_out0 = devptr(g_out0);
    float* p_out1 = devptr(g_out1);
    float* p_q    = devptr(g_q);
    float* p_k    = devptr(g_k);
    float* p_v    = devptr(g_v);
    float* p_attn = devptr(g_attn);
    float* p_ctx  = devptr(g_ctx);
    float* p_r    = devptr(g_r);
    float* p_wcT  = devptr(g_wcT);
    float* p_ih0f = devptr(g_wih0fT);
    float* p_ih0b = devptr(g_wih0bT);
    float* p_ih1f = devptr(g_wih1fT);
    float* p_ih1b = devptr(g_wih1bT);
    float* p_hh0f = devptr(g_whh0fI);
    float* p_hh0b = devptr(g_whh0bI);
    float* p_hh1f = devptr(g_whh1fI);
    float* p_hh1b = devptr(g_whh1bI);
    float* p_wqT  = devptr(g_wqT);
    float* p_wkT  = devptr(g_wkT);
    float* p_wvT  = devptr(g_wvT);

    const int M = B_*S_;  // 32768

    // weight reshapes
    convw_t_k<<<(C_*16*C_+255)/256, 256>>>(conv_w, p_wcT);
    transpose_k<<<(G4_*C_+255)/256, 256>>>(W_ih0f, p_ih0f, G4_, C_);
    transpose_k<<<(G4_*C_+255)/256, 256>>>(W_ih0b, p_ih0b, G4_, C_);
    transpose_k<<<(G4_*D2_+255)/256, 256>>>(W_ih1f, p_ih1f, G4_, D2_);
    transpose_k<<<(G4_*D2_+255)/256, 256>>>(W_ih1b, p_ih1b, G4_, D2_);
    whh_int_k<<<(HID_*G4_+255)/256, 256>>>(W_hh0f, p_hh0f);
    whh_int_k<<<(HID_*G4_+255)/256, 256>>>(W_hh0b, p_hh0b);
    whh_int_k<<<(HID_*G4_+255)/256, 256>>>(W_hh1f, p_hh1f);
    whh_int_k<<<(HID_*G4_+255)/256, 256>>>(W_hh1b, p_hh1b);
    transpose_k<<<(D2_*D2_+255)/256, 256>>>(Wq, p_wqT, D2_, D2_);
    transpose_k<<<(D2_*D2_+255)/256, 256>>>(Wk, p_wkT, D2_, D2_);
    transpose_k<<<(D2_*D2_+255)/256, 256>>>(Wv, p_wvT, D2_, D2_);

    // conv front-end
    conv_bn_pool_k<<<dim3(S_/4, B_), 128>>>(x, p_wcT, conv_b, bn_g, bn_b, bn_m, bn_v, p_h0);

    // layer 0 gates + recurrence
    sgemm_bias_k<<<dim3(G4_/128, M/128), 256>>>(p_h0, p_ih0f, b0f, p_xgf, M, G4_, C_);
    sgemm_bias_k<<<dim3(G4_/128, M/128), 256>>>(p_h0, p_ih0b, b0b, p_xgb, M, G4_, C_);
    lstm_k<<<dim3(B_/2, 2), 256>>>(p_xgf, p_xgb, p_hh0f, p_hh0b, p_out0);

    // layer 1 gates + recurrence
    sgemm_bias_k<<<dim3(G4_/128, M/128), 256>>>(p_out0, p_ih1f, b1f, p_xgf, M, G4_, D2_);
    sgemm_bias_k<<<dim3(G4_/128, M/128), 256>>>(p_out0, p_ih1b, b1b, p_xgb, M, G4_, D2_);
    lstm_k<<<dim3(B_/2, 2), 256>>>(p_xgf, p_xgb, p_hh1f, p_hh1b, p_out1);

    // QKV
    sgemm_bias_k<<<dim3(D2_/128, M/128), 256>>>(p_out1, p_wqT, bq, p_q, M, D2_, D2_);
    sgemm_bias_k<<<dim3(D2_/128, M/128), 256>>>(p_out1, p_wkT, bk, p_k, M, D2_, D2_);
    sgemm_bias_k<<<dim3(D2_/128, M/128), 256>>>(p_out1, p_wvT, bv, p_v, M, D2_, D2_);

    // attention
    attn_scores_k<<<dim3(S_/64, S_/64, B_*NH_), 256>>>(p_q, p_k, p_attn);
    logsoftmax_h_k<<<(int)(((size_t)B_*S_*S_ + 255)/256), 256>>>(p_attn);
    attn_ctx_k<<<dim3(S_/64, B_*NH_), 256>>>(p_attn, p_v, p_ctx);

    // residual + LN + pool + fc
    res_ln_k<<<M, 256>>>(p_out1, p_ctx, ln_g, ln_b, p_r);
    pool_fc_k<<<B_, 256>>>(p_r, fc_w, fc_b, out);

    (void)in_sizes; (void)n_in; (void)out_size;
}